// round 9
// baseline (speedup 1.0000x reference)
#include <cuda_runtime.h>

// Problem dims
#define BATCH 512
#define LSEQ  256     // H*W = 16*16
#define CIN   32
#define HID   128
#define OUTD  512

// ---------------- scratch (static device globals; no runtime allocation) ---
__device__ float d_Wc[HID * CIN];                       // folded W_ih @ W_in  (128x32)
__device__ float d_bc[HID];                             // folded bias (incl. b_hh)
__device__ float d_pre[(size_t)BATCH * LSEQ * HID];     // 64 MB, layout [b][t][j]
__device__ float d_hs [(size_t)BATCH * LSEQ * HID];     // 64 MB, layout [b][t][j]
__device__ float d_pooled[BATCH * HID];

// ---------------- f32x2 helpers (Blackwell packed fp32 FMA) ----------------
__device__ __forceinline__ unsigned long long pack2(float a, float b) {
    unsigned long long r;
    asm("mov.b64 %0, {%1, %2};" : "=l"(r) : "f"(a), "f"(b));
    return r;
}
__device__ __forceinline__ void unpack2(unsigned long long v, float& a, float& b) {
    asm("mov.b64 {%0, %1}, %2;" : "=f"(a), "=f"(b) : "l"(v));
}
__device__ __forceinline__ void ffma2(unsigned long long& acc,
                                      unsigned long long a, unsigned long long b) {
    asm("fma.rn.f32x2 %0, %1, %2, %0;" : "+l"(acc) : "l"(a), "l"(b));
}
__device__ __forceinline__ unsigned long long fadd2(unsigned long long a,
                                                    unsigned long long b) {
    unsigned long long r;
    asm("add.rn.f32x2 %0, %1, %2;" : "=l"(r) : "l"(a), "l"(b));
    return r;
}

// ---------------------------------------------------------------------------
// Kernel A: fold the two input linears + b_hh.
// ---------------------------------------------------------------------------
__global__ void combine_kernel(const float* __restrict__ W_in,
                               const float* __restrict__ b_in,
                               const float* __restrict__ W_ih,
                               const float* __restrict__ b_ih,
                               const float* __restrict__ b_hh) {
    int idx = blockIdx.x * blockDim.x + threadIdx.x;
    if (idx < HID * CIN) {
        int j = idx >> 5, c = idx & 31;
        float s = 0.f;
        #pragma unroll 8
        for (int m = 0; m < 64; m++) s += W_ih[j * 64 + m] * W_in[m * 32 + c];
        d_Wc[idx] = s;
    }
    if (idx < HID) {
        float s = b_ih[idx] + b_hh[idx];
        #pragma unroll 8
        for (int m = 0; m < 64; m++) s += W_ih[idx * 64 + m] * b_in[m];
        d_bc[idx] = s;
    }
}

// ---------------------------------------------------------------------------
// Kernel B: pre[b][t][j] = bc[j] + sum_c Wc[j][c] * x[b][c][t]
// ---------------------------------------------------------------------------
__global__ void __launch_bounds__(256) pre_kernel(const float* __restrict__ x) {
    __shared__ __align__(16) float xs[32 * 32];   // [c][tt]
    int tid = threadIdx.x;
    int b = blockIdx.y;
    int t0 = blockIdx.x * 32;

    #pragma unroll
    for (int i = 0; i < 4; i++) {
        int idx = i * 256 + tid;
        int c = idx >> 5, tt = idx & 31;
        xs[idx] = x[(b * 32 + c) * 256 + t0 + tt];
    }

    int j = tid & 127;
    int th = tid >> 7;

    unsigned long long wd[32];
    #pragma unroll
    for (int c4 = 0; c4 < 8; c4++) {
        float4 w = *(const float4*)&d_Wc[j * 32 + c4 * 4];
        wd[c4 * 4 + 0] = pack2(w.x, w.x);
        wd[c4 * 4 + 1] = pack2(w.y, w.y);
        wd[c4 * 4 + 2] = pack2(w.z, w.z);
        wd[c4 * 4 + 3] = pack2(w.w, w.w);
    }
    float bcj = d_bc[j];
    unsigned long long bias2 = pack2(bcj, bcj);

    __syncthreads();

    int tbase = th * 16;
    #pragma unroll
    for (int pp = 0; pp < 4; pp++) {
        unsigned long long acc0 = bias2, acc1 = bias2;
        const float* xb = xs + tbase + 4 * pp;
        #pragma unroll
        for (int c = 0; c < 32; c++) {
            ulonglong2 xv = *(const ulonglong2*)(xb + c * 32);
            ffma2(acc0, wd[c], xv.x);
            ffma2(acc1, wd[c], xv.y);
        }
        float v0, v1, v2, v3;
        unpack2(acc0, v0, v1);
        unpack2(acc1, v2, v3);
        int t = t0 + tbase + 4 * pp;
        d_pre[(b * 256 + t + 0) * 128 + j] = v0;
        d_pre[(b * 256 + t + 1) * 128 + j] = v1;
        d_pre[(b * 256 + t + 2) * 128 + j] = v2;
        d_pre[(b * 256 + t + 3) * 128 + j] = v3;
    }
}

// ---------------------------------------------------------------------------
// Kernel C: sequential RNN scan (R6 layout), split in two halves (profiling),
// PLUS anti-phase stagger: classic placement maps bid and bid+148 to the same
// SM; the second CTA spins ~600 cyc once so its FMA bursts interleave with its
// SM-mate's reduce/tanh/barrier tail instead of phase-locking with it.
// ---------------------------------------------------------------------------
__global__ void __launch_bounds__(128, 2) rnn_kernel(const float* __restrict__ h0,
                                                     const float* __restrict__ W_hh,
                                                     int t_first, int t_count) {
    __shared__ __align__(16) float hsm[2][2 * 144];

    int tid = threadIdx.x;
    int kc = tid & 3;
    int jg = tid >> 2;          // 0..31
    int r0 = blockIdx.x * 2;

    // W slices: 4 j rows x 32 k as f32x2 pairs (128 regs)
    unsigned long long wp[4][16];
    #pragma unroll
    for (int jj = 0; jj < 4; jj++) {
        const float* wrow = W_hh + (jj * 32 + jg) * 128 + kc * 32;
        #pragma unroll
        for (int i = 0; i < 8; i++) {
            float4 w = *(const float4*)(wrow + i * 4);
            wp[jj][2 * i]     = pack2(w.x, w.y);
            wp[jj][2 * i + 1] = pack2(w.z, w.w);
        }
    }

    // init h state: from h0 for the first segment, else from d_hs[t_first-1]
    for (int i = tid; i < 256; i += 128) {
        int r = i >> 7, k = i & 127;
        float v;
        if (t_first == 0) v = h0[(r0 + r) * 128 + k];
        else              v = d_hs[(size_t)(r0 + r) * 32768 + (t_first - 1) * 128 + k];
        hsm[0][r * 144 + (k >> 5) * 36 + (k & 31)] = v;
    }
    __syncthreads();

    // ---- anti-phase seed: second CTA on each SM delays ~half a step ----
    if (blockIdx.x >= 148) {
        unsigned long long s0 = clock64();
        while (clock64() - s0 < 600ull) { }
    }

    int j_sel = kc * 32 + jg;
    const float* pA = d_pre + (size_t)r0 * 32768 + j_sel + (size_t)t_first * 128;
    const float* pB = d_pre + (size_t)(r0 + 1) * 32768 + j_sel + (size_t)t_first * 128;
    float* oA = d_hs + (size_t)r0 * 32768 + j_sel + (size_t)t_first * 128;
    float* oB = d_hs + (size_t)(r0 + 1) * 32768 + j_sel + (size_t)t_first * 128;

    int offA = kc * 36;                 // h-slice offset, row 0
    int offB = 144 + kc * 36;           // row 1
    int stA = kc * 36 + jg;             // STS slots
    int stB = 144 + kc * 36 + jg;

    float pvA = pA[0], pvB = pB[0];
    bool bit0 = (kc & 1), bit1 = (kc & 2);

    for (int s = 0; s < t_count; s++) {
        int sn = (s + 1 < t_count) ? (s + 1) : s;
        float npA = pA[sn * 128];          // prefetch next step's pre
        float npB = pB[sn * 128];

        const float* rbuf = hsm[s & 1];
        float* wbuf = hsm[(s + 1) & 1];

        // ---- partials, rows A and B (independent; full FMA burst) ----
        float sAr[4], sBr[4];
        {
            const ulonglong2* hbA = (const ulonglong2*)(rbuf + offA);
            ulonglong2 hv[8];
            #pragma unroll
            for (int i = 0; i < 8; i++) hv[i] = hbA[i];
            #pragma unroll
            for (int jj = 0; jj < 4; jj++) {
                unsigned long long a0 = 0ull, a1 = 0ull;
                #pragma unroll
                for (int i = 0; i < 8; i++) {
                    ffma2(a0, wp[jj][2 * i],     hv[i].x);
                    ffma2(a1, wp[jj][2 * i + 1], hv[i].y);
                }
                unsigned long long as = fadd2(a0, a1);
                float lo, hi; unpack2(as, lo, hi);
                sAr[jj] = lo + hi;
            }
        }
        {
            const ulonglong2* hbB = (const ulonglong2*)(rbuf + offB);
            ulonglong2 hv[8];
            #pragma unroll
            for (int i = 0; i < 8; i++) hv[i] = hbB[i];
            #pragma unroll
            for (int jj = 0; jj < 4; jj++) {
                unsigned long long a0 = 0ull, a1 = 0ull;
                #pragma unroll
                for (int i = 0; i < 8; i++) {
                    ffma2(a0, wp[jj][2 * i],     hv[i].x);
                    ffma2(a1, wp[jj][2 * i + 1], hv[i].y);
                }
                unsigned long long as = fadd2(a0, a1);
                float lo, hi; unpack2(as, lo, hi);
                sBr[jj] = lo + hi;
            }
        }

        // ---- reduce-scatter over kc lanes + tanh, both rows ----
        float A_t0 = (bit0 ? sAr[1] : sAr[0]) + __shfl_xor_sync(~0u, bit0 ? sAr[0] : sAr[1], 1);
        float A_t1 = (bit0 ? sAr[3] : sAr[2]) + __shfl_xor_sync(~0u, bit0 ? sAr[2] : sAr[3], 1);
        float B_t0 = (bit0 ? sBr[1] : sBr[0]) + __shfl_xor_sync(~0u, bit0 ? sBr[0] : sBr[1], 1);
        float B_t1 = (bit0 ? sBr[3] : sBr[2]) + __shfl_xor_sync(~0u, bit0 ? sBr[2] : sBr[3], 1);
        float selA = (bit1 ? A_t1 : A_t0) + __shfl_xor_sync(~0u, bit1 ? A_t0 : A_t1, 2);
        float selB = (bit1 ? B_t1 : B_t0) + __shfl_xor_sync(~0u, bit1 ? B_t0 : B_t1, 2);

        float zA = selA + pvA;
        float zB = selB + pvB;
        float eA = __expf(2.0f * zA);
        float eB = __expf(2.0f * zB);
        float hAv = 1.0f - __fdividef(2.0f, eA + 1.0f);
        float hBv = 1.0f - __fdividef(2.0f, eB + 1.0f);

        wbuf[stA] = hAv;                  // no WAR hazard (double buffer)
        wbuf[stB] = hBv;
        oA[s * 128] = hAv;
        oB[s * 128] = hBv;

        __syncthreads();                  // RAW: h visible for next step

        pvA = npA; pvB = npB;
    }
}

// ---------------------------------------------------------------------------
// Kernel D: bilinear upsample (16->32, align_corners) + hardswish + mean pool.
// smem tile [jj][t], stride 261 -> conflict-free transposed stores and reads.
// ---------------------------------------------------------------------------
__global__ void __launch_bounds__(256) pool_kernel() {
    __shared__ float ht[32 * 261];
    __shared__ float partial[8][32];

    int tid = threadIdx.x;
    int b  = blockIdx.y;
    int j0 = blockIdx.x * 32;

    #pragma unroll
    for (int i = 0; i < 8; i++) {
        int idx4 = i * 256 + tid;
        int t = idx4 >> 3, q = idx4 & 7;
        float4 v = *(const float4*)&d_hs[((size_t)b * 256 + t) * 128 + j0 + q * 4];
        ht[(q * 4 + 0) * 261 + t] = v.x;
        ht[(q * 4 + 1) * 261 + t] = v.y;
        ht[(q * 4 + 2) * 261 + t] = v.z;
        ht[(q * 4 + 3) * 261 + t] = v.w;
    }
    __syncthreads();

    int jj = tid & 31, p = tid >> 5;
    const float* hrow = ht + jj * 261;
    float acc = 0.f;

    #pragma unroll
    for (int q = 0; q < 4; q++) {
        int oy = p * 4 + q;
        float ysf = (float)(oy * 15) / 31.0f;
        int y0 = (int)ysf;
        float wy = ysf - (float)y0;
        int y1 = min(y0 + 1, 15);

        const float* pa = hrow + y0 * 16;
        const float* pb = hrow + y1 * 16;
        float rv[16];
        #pragma unroll
        for (int xq = 0; xq < 16; xq++) {
            float a = pa[xq], c = pb[xq];
            rv[xq] = fmaf(c - a, wy, a);
        }

        #pragma unroll
        for (int ox = 0; ox < 32; ox++) {
            const int x0 = (ox * 15) / 31;
            const int x1 = (x0 + 1 < 16) ? (x0 + 1) : 15;
            const float wx = (float)(ox * 15) / 31.0f - (float)x0;
            float v = fmaf(rv[x1] - rv[x0], wx, rv[x0]);
            acc = fmaf(v, fminf(fmaxf(v + 3.0f, 0.0f), 6.0f), acc);
        }
    }

    partial[p][jj] = acc;
    __syncthreads();
    if (p == 0) {
        float s = 0.f;
        #pragma unroll
        for (int q = 0; q < 8; q++) s += partial[q][jj];
        d_pooled[b * 128 + j0 + jj] = s * (1.0f / (6.0f * 1024.0f));
    }
}

// ---------------------------------------------------------------------------
// Kernel E: out[b][o] = b_out[o] + sum_j pooled[b][j] * W_out[o][j]
// ---------------------------------------------------------------------------
__global__ void __launch_bounds__(256) out_gemm(const float* __restrict__ W_out,
                                                const float* __restrict__ b_out,
                                                float* __restrict__ out) {
    __shared__ float ws[64][65];
    __shared__ float ps[64][65];

    int tid = threadIdx.x;
    int o0 = blockIdx.x * 64, b0 = blockIdx.y * 64;
    int to = (tid & 15) * 4;
    int tb = (tid >> 4) * 4;

    float acc[4][4] = {};

    for (int k0 = 0; k0 < 128; k0 += 64) {
        __syncthreads();
        #pragma unroll
        for (int i = 0; i < 16; i++) {
            int idx = i * 256 + tid;
            int r = idx >> 6, c = idx & 63;
            ws[r][c] = W_out[(o0 + r) * 128 + k0 + c];
            ps[r][c] = d_pooled[(b0 + r) * 128 + k0 + c];
        }
        __syncthreads();

        #pragma unroll 4
        for (int k = 0; k < 64; k++) {
            float wv[4], pvv[4];
            #pragma unroll
            for (int m = 0; m < 4; m++) { wv[m] = ws[to + m][k]; pvv[m] = ps[tb + m][k]; }
            #pragma unroll
            for (int mb = 0; mb < 4; mb++)
                #pragma unroll
                for (int mo = 0; mo < 4; mo++)
                    acc[mb][mo] = fmaf(pvv[mb], wv[mo], acc[mb][mo]);
        }
    }

    #pragma unroll
    for (int mb = 0; mb < 4; mb++)
        #pragma unroll
        for (int mo = 0; mo < 4; mo++)
            out[(b0 + tb + mb) * 512 + o0 + to + mo] = acc[mb][mo] + b_out[o0 + to + mo];
}

// ---------------------------------------------------------------------------
extern "C" void kernel_launch(void* const* d_in, const int* in_sizes, int n_in,
                              void* d_out, int out_size) {
    const float* x     = (const float*)d_in[0];
    const float* h0    = (const float*)d_in[1];
    const float* W_in  = (const float*)d_in[2];
    const float* b_in  = (const float*)d_in[3];
    const float* W_ih  = (const float*)d_in[4];
    const float* b_ih  = (const float*)d_in[5];
    const float* W_hh  = (const float*)d_in[6];
    const float* b_hh  = (const float*)d_in[7];
    const float* W_out = (const float*)d_in[8];
    const float* b_out = (const float*)d_in[9];
    float* out = (float*)d_out;

    combine_kernel<<<16, 256>>>(W_in, b_in, W_ih, b_ih, b_hh);
    pre_kernel<<<dim3(8, 512), 256>>>(x);
    rnn_kernel<<<256, 128>>>(h0, W_hh, 0, 128);     // t = 0..127
    rnn_kernel<<<256, 128>>>(h0, W_hh, 128, 128);   // t = 128..255 (ncu slot)
    pool_kernel<<<dim3(4, 512), 256>>>();
    out_gemm<<<dim3(8, 8), 256>>>(W_out, b_out, out);
}

// round 10
// speedup vs baseline: 1.2718x; 1.2718x over previous
#include <cuda_runtime.h>

// Problem dims
#define BATCH 512
#define LSEQ  256     // H*W = 16*16
#define CIN   32
#define HID   128
#define OUTD  512

// ---------------- scratch (static device globals; no runtime allocation) ---
__device__ float d_Wc[HID * CIN];                       // folded W_ih @ W_in  (128x32)
__device__ float d_bc[HID];                             // folded bias (incl. b_hh)
__device__ float d_hs [(size_t)BATCH * LSEQ * HID];     // 64 MB, layout [b][t][j]
__device__ float d_pooled[BATCH * HID];

// ---------------- f32x2 helpers (Blackwell packed fp32 FMA) ----------------
__device__ __forceinline__ unsigned long long pack2(float a, float b) {
    unsigned long long r;
    asm("mov.b64 %0, {%1, %2};" : "=l"(r) : "f"(a), "f"(b));
    return r;
}
__device__ __forceinline__ void unpack2(unsigned long long v, float& a, float& b) {
    asm("mov.b64 {%0, %1}, %2;" : "=f"(a), "=f"(b) : "l"(v));
}
__device__ __forceinline__ void ffma2(unsigned long long& acc,
                                      unsigned long long a, unsigned long long b) {
    asm("fma.rn.f32x2 %0, %1, %2, %0;" : "+l"(acc) : "l"(a), "l"(b));
}
__device__ __forceinline__ unsigned long long fadd2(unsigned long long a,
                                                    unsigned long long b) {
    unsigned long long r;
    asm("add.rn.f32x2 %0, %1, %2;" : "=l"(r) : "l"(a), "l"(b));
    return r;
}

// ---------------------------------------------------------------------------
// Kernel A: fold the two input linears + b_hh.
// ---------------------------------------------------------------------------
__global__ void combine_kernel(const float* __restrict__ W_in,
                               const float* __restrict__ b_in,
                               const float* __restrict__ W_ih,
                               const float* __restrict__ b_ih,
                               const float* __restrict__ b_hh) {
    int idx = blockIdx.x * blockDim.x + threadIdx.x;
    if (idx < HID * CIN) {
        int j = idx >> 5, c = idx & 31;
        float s = 0.f;
        #pragma unroll 8
        for (int m = 0; m < 64; m++) s += W_ih[j * 64 + m] * W_in[m * 32 + c];
        d_Wc[idx] = s;
    }
    if (idx < HID) {
        float s = b_ih[idx] + b_hh[idx];
        #pragma unroll 8
        for (int m = 0; m < 64; m++) s += W_ih[idx * 64 + m] * b_in[m];
        d_bc[idx] = s;
    }
}

// ---------------------------------------------------------------------------
// Kernel C: fused input-projection + sequential RNN scan.
//   h_t = tanh( Wc @ x[:, :, t] + bc  +  W_hh @ h_{t-1} )
// 256 CTAs x 2 batch rows, 128 threads, 2 CTAs/SM. tid = jg*4 + kc.
// Thread (jg,kc) owns W_hh for j in {jg, jg+32, jg+64, jg+96} (128 regs) and
// Wc[j_sel][0..31] (32 regs), j_sel = kc*32+jg. The input projection
// (32 MACs/row/step) is computed in-step from an x tile staged in smem
// (double-buffered, reloaded every 16 steps, broadcast reads) — this removes
// the d_pre 64MB write+read round trip AND the per-step DRAM-latency LDG.
// Double-buffered h, single RAW barrier per step.
// ---------------------------------------------------------------------------
__global__ void __launch_bounds__(128, 2) rnn_kernel(const float* __restrict__ x,
                                                     const float* __restrict__ h0,
                                                     const float* __restrict__ W_hh,
                                                     int t_first, int t_count) {
    __shared__ __align__(16) float hsm[2][2 * 144];
    __shared__ __align__(16) float xsm[2][2][16][36];   // [buf][row][tt][c]

    int tid = threadIdx.x;
    int kc = tid & 3;
    int jg = tid >> 2;          // 0..31
    int r0 = blockIdx.x * 2;

    // W_hh slices: 4 j rows x 32 k as f32x2 pairs (128 regs)
    unsigned long long wp[4][16];
    #pragma unroll
    for (int jj = 0; jj < 4; jj++) {
        const float* wrow = W_hh + (jj * 32 + jg) * 128 + kc * 32;
        #pragma unroll
        for (int i = 0; i < 8; i++) {
            float4 w = *(const float4*)(wrow + i * 4);
            wp[jj][2 * i]     = pack2(w.x, w.y);
            wp[jj][2 * i + 1] = pack2(w.z, w.w);
        }
    }

    int j_sel = kc * 32 + jg;

    // Wc row for the finalized j (16 pairs = 32 regs) + bias
    unsigned long long wcp[16];
    #pragma unroll
    for (int i = 0; i < 8; i++) {
        float4 w = *(const float4*)&d_Wc[j_sel * 32 + i * 4];
        wcp[2 * i]     = pack2(w.x, w.y);
        wcp[2 * i + 1] = pack2(w.z, w.w);
    }
    float bcj = d_bc[j_sel];

    // init h state: from h0 for the first segment, else from d_hs[t_first-1]
    for (int i = tid; i < 256; i += 128) {
        int r = i >> 7, k = i & 127;
        float v;
        if (t_first == 0) v = h0[(r0 + r) * 128 + k];
        else              v = d_hs[(size_t)(r0 + r) * 32768 + (t_first - 1) * 128 + k];
        hsm[0][r * 144 + (k >> 5) * 36 + (k & 31)] = v;
    }

    // x tile loader: thread (r = tid>>6, half = (tid>>5)&1, c = tid&31)
    // loads x[b_r][c][t0 + half*8 .. +8) and transposes into xsm[buf].
    int xr = tid >> 6, xhalf = (tid >> 5) & 1, xc = tid & 31;
    const float* xbase = x + ((size_t)(r0 + xr) * 32 + xc) * 256 + xhalf * 8;

    // initial tile for the first epoch
    {
        int t0 = t_first;
        float4 v0 = *(const float4*)(xbase + t0);
        float4 v1 = *(const float4*)(xbase + t0 + 4);
        float* xd = &xsm[(t0 >> 4) & 1][xr][xhalf * 8][xc];
        xd[0 * 36] = v0.x; xd[1 * 36] = v0.y; xd[2 * 36] = v0.z; xd[3 * 36] = v0.w;
        xd[4 * 36] = v1.x; xd[5 * 36] = v1.y; xd[6 * 36] = v1.z; xd[7 * 36] = v1.w;
    }
    __syncthreads();

    float* oA = d_hs + (size_t)r0 * 32768 + j_sel + (size_t)t_first * 128;
    float* oB = d_hs + (size_t)(r0 + 1) * 32768 + j_sel + (size_t)t_first * 128;

    int offA = kc * 36;                 // h-slice offset, row 0
    int offB = 144 + kc * 36;           // row 1
    int stA = kc * 36 + jg;             // STS slots
    int stB = 144 + kc * 36 + jg;

    bool bit0 = (kc & 1), bit1 = (kc & 2);
    int t_end = t_first + t_count;

    for (int s = 0; s < t_count; s++) {
        int t = t_first + s;
        int tt = t & 15;
        int e = t >> 4;

        // prefetch next x epoch (safe: all warps passed the prior barrier,
        // so nobody is still reading buf (e+1)&1, last used 16+ steps ago)
        if (tt == 0 && (t + 16) < t_end) {
            int t0 = t + 16;
            float4 v0 = *(const float4*)(xbase + t0);
            float4 v1 = *(const float4*)(xbase + t0 + 4);
            float* xd = &xsm[(e + 1) & 1][xr][xhalf * 8][xc];
            xd[0 * 36] = v0.x; xd[1 * 36] = v0.y; xd[2 * 36] = v0.z; xd[3 * 36] = v0.w;
            xd[4 * 36] = v1.x; xd[5 * 36] = v1.y; xd[6 * 36] = v1.z; xd[7 * 36] = v1.w;
        }

        const float* rbuf = hsm[t & 1];
        float* wbuf = hsm[(t + 1) & 1];

        // ---- input projection for this step (independent of h; broadcast) --
        float preA, preB;
        {
            const ulonglong2* xA = (const ulonglong2*)&xsm[e & 1][0][tt][0];
            const ulonglong2* xB = (const ulonglong2*)&xsm[e & 1][1][tt][0];
            unsigned long long a0 = 0ull, a1 = 0ull, b0 = 0ull, b1 = 0ull;
            #pragma unroll
            for (int i = 0; i < 4; i++) {
                ulonglong2 va = xA[2 * i], va2 = xA[2 * i + 1];
                ulonglong2 vb = xB[2 * i], vb2 = xB[2 * i + 1];
                ffma2(a0, wcp[4 * i],     va.x);
                ffma2(a1, wcp[4 * i + 1], va.y);
                ffma2(a0, wcp[4 * i + 2], va2.x);
                ffma2(a1, wcp[4 * i + 3], va2.y);
                ffma2(b0, wcp[4 * i],     vb.x);
                ffma2(b1, wcp[4 * i + 1], vb.y);
                ffma2(b0, wcp[4 * i + 2], vb2.x);
                ffma2(b1, wcp[4 * i + 3], vb2.y);
            }
            unsigned long long as = fadd2(a0, a1), bs = fadd2(b0, b1);
            float lo, hi;
            unpack2(as, lo, hi); preA = bcj + lo + hi;
            unpack2(bs, lo, hi); preB = bcj + lo + hi;
        }

        // ---- recurrent partials, rows A and B ----
        float sAr[4], sBr[4];
        {
            const ulonglong2* hbA = (const ulonglong2*)(rbuf + offA);
            ulonglong2 hv[8];
            #pragma unroll
            for (int i = 0; i < 8; i++) hv[i] = hbA[i];
            #pragma unroll
            for (int jj = 0; jj < 4; jj++) {
                unsigned long long a0 = 0ull, a1 = 0ull;
                #pragma unroll
                for (int i = 0; i < 8; i++) {
                    ffma2(a0, wp[jj][2 * i],     hv[i].x);
                    ffma2(a1, wp[jj][2 * i + 1], hv[i].y);
                }
                unsigned long long as = fadd2(a0, a1);
                float lo, hi; unpack2(as, lo, hi);
                sAr[jj] = lo + hi;
            }
        }
        {
            const ulonglong2* hbB = (const ulonglong2*)(rbuf + offB);
            ulonglong2 hv[8];
            #pragma unroll
            for (int i = 0; i < 8; i++) hv[i] = hbB[i];
            #pragma unroll
            for (int jj = 0; jj < 4; jj++) {
                unsigned long long a0 = 0ull, a1 = 0ull;
                #pragma unroll
                for (int i = 0; i < 8; i++) {
                    ffma2(a0, wp[jj][2 * i],     hv[i].x);
                    ffma2(a1, wp[jj][2 * i + 1], hv[i].y);
                }
                unsigned long long as = fadd2(a0, a1);
                float lo, hi; unpack2(as, lo, hi);
                sBr[jj] = lo + hi;
            }
        }

        // ---- reduce-scatter over kc lanes + tanh, both rows ----
        float A_t0 = (bit0 ? sAr[1] : sAr[0]) + __shfl_xor_sync(~0u, bit0 ? sAr[0] : sAr[1], 1);
        float A_t1 = (bit0 ? sAr[3] : sAr[2]) + __shfl_xor_sync(~0u, bit0 ? sAr[2] : sAr[3], 1);
        float B_t0 = (bit0 ? sBr[1] : sBr[0]) + __shfl_xor_sync(~0u, bit0 ? sBr[0] : sBr[1], 1);
        float B_t1 = (bit0 ? sBr[3] : sBr[2]) + __shfl_xor_sync(~0u, bit0 ? sBr[2] : sBr[3], 1);
        float selA = (bit1 ? A_t1 : A_t0) + __shfl_xor_sync(~0u, bit1 ? A_t0 : A_t1, 2);
        float selB = (bit1 ? B_t1 : B_t0) + __shfl_xor_sync(~0u, bit1 ? B_t0 : B_t1, 2);

        float zA = selA + preA;
        float zB = selB + preB;
        float eA = __expf(2.0f * zA);
        float eB = __expf(2.0f * zB);
        float hAv = 1.0f - __fdividef(2.0f, eA + 1.0f);
        float hBv = 1.0f - __fdividef(2.0f, eB + 1.0f);

        wbuf[stA] = hAv;                  // double buffer: no WAR hazard
        wbuf[stB] = hBv;
        oA[s * 128] = hAv;
        oB[s * 128] = hBv;

        __syncthreads();                  // RAW: h(t) + staged x visible

    }
}

// ---------------------------------------------------------------------------
// Kernel D: bilinear upsample (16->32, align_corners) + hardswish + mean pool.
// smem tile [jj][t], stride 261 -> conflict-free transposed stores and reads.
// ---------------------------------------------------------------------------
__global__ void __launch_bounds__(256) pool_kernel() {
    __shared__ float ht[32 * 261];
    __shared__ float partial[8][32];

    int tid = threadIdx.x;
    int b  = blockIdx.y;
    int j0 = blockIdx.x * 32;

    #pragma unroll
    for (int i = 0; i < 8; i++) {
        int idx4 = i * 256 + tid;
        int t = idx4 >> 3, q = idx4 & 7;
        float4 v = *(const float4*)&d_hs[((size_t)b * 256 + t) * 128 + j0 + q * 4];
        ht[(q * 4 + 0) * 261 + t] = v.x;
        ht[(q * 4 + 1) * 261 + t] = v.y;
        ht[(q * 4 + 2) * 261 + t] = v.z;
        ht[(q * 4 + 3) * 261 + t] = v.w;
    }
    __syncthreads();

    int jj = tid & 31, p = tid >> 5;
    const float* hrow = ht + jj * 261;
    float acc = 0.f;

    #pragma unroll
    for (int q = 0; q < 4; q++) {
        int oy = p * 4 + q;
        float ysf = (float)(oy * 15) / 31.0f;
        int y0 = (int)ysf;
        float wy = ysf - (float)y0;
        int y1 = min(y0 + 1, 15);

        const float* pa = hrow + y0 * 16;
        const float* pb = hrow + y1 * 16;
        float rv[16];
        #pragma unroll
        for (int xq = 0; xq < 16; xq++) {
            float a = pa[xq], c = pb[xq];
            rv[xq] = fmaf(c - a, wy, a);
        }

        #pragma unroll
        for (int ox = 0; ox < 32; ox++) {
            const int x0 = (ox * 15) / 31;
            const int x1 = (x0 + 1 < 16) ? (x0 + 1) : 15;
            const float wx = (float)(ox * 15) / 31.0f - (float)x0;
            float v = fmaf(rv[x1] - rv[x0], wx, rv[x0]);
            acc = fmaf(v, fminf(fmaxf(v + 3.0f, 0.0f), 6.0f), acc);
        }
    }

    partial[p][jj] = acc;
    __syncthreads();
    if (p == 0) {
        float s = 0.f;
        #pragma unroll
        for (int q = 0; q < 8; q++) s += partial[q][jj];
        d_pooled[b * 128 + j0 + jj] = s * (1.0f / (6.0f * 1024.0f));
    }
}

// ---------------------------------------------------------------------------
// Kernel E: out[b][o] = b_out[o] + sum_j pooled[b][j] * W_out[o][j]
// ---------------------------------------------------------------------------
__global__ void __launch_bounds__(256) out_gemm(const float* __restrict__ W_out,
                                                const float* __restrict__ b_out,
                                                float* __restrict__ out) {
    __shared__ float ws[64][65];
    __shared__ float ps[64][65];

    int tid = threadIdx.x;
    int o0 = blockIdx.x * 64, b0 = blockIdx.y * 64;
    int to = (tid & 15) * 4;
    int tb = (tid >> 4) * 4;

    float acc[4][4] = {};

    for (int k0 = 0; k0 < 128; k0 += 64) {
        __syncthreads();
        #pragma unroll
        for (int i = 0; i < 16; i++) {
            int idx = i * 256 + tid;
            int r = idx >> 6, c = idx & 63;
            ws[r][c] = W_out[(o0 + r) * 128 + k0 + c];
            ps[r][c] = d_pooled[(b0 + r) * 128 + k0 + c];
        }
        __syncthreads();

        #pragma unroll 4
        for (int k = 0; k < 64; k++) {
            float wv[4], pvv[4];
            #pragma unroll
            for (int m = 0; m < 4; m++) { wv[m] = ws[to + m][k]; pvv[m] = ps[tb + m][k]; }
            #pragma unroll
            for (int mb = 0; mb < 4; mb++)
                #pragma unroll
                for (int mo = 0; mo < 4; mo++)
                    acc[mb][mo] = fmaf(pvv[mb], wv[mo], acc[mb][mo]);
        }
    }

    #pragma unroll
    for (int mb = 0; mb < 4; mb++)
        #pragma unroll
        for (int mo = 0; mo < 4; mo++)
            out[(b0 + tb + mb) * 512 + o0 + to + mo] = acc[mb][mo] + b_out[o0 + to + mo];
}

// ---------------------------------------------------------------------------
extern "C" void kernel_launch(void* const* d_in, const int* in_sizes, int n_in,
                              void* d_out, int out_size) {
    const float* x     = (const float*)d_in[0];
    const float* h0    = (const float*)d_in[1];
    const float* W_in  = (const float*)d_in[2];
    const float* b_in  = (const float*)d_in[3];
    const float* W_ih  = (const float*)d_in[4];
    const float* b_ih  = (const float*)d_in[5];
    const float* W_hh  = (const float*)d_in[6];
    const float* b_hh  = (const float*)d_in[7];
    const float* W_out = (const float*)d_in[8];
    const float* b_out = (const float*)d_in[9];
    float* out = (float*)d_out;

    combine_kernel<<<16, 256>>>(W_in, b_in, W_ih, b_ih, b_hh);
    rnn_kernel<<<256, 128>>>(x, h0, W_hh, 0, 128);     // t = 0..127
    rnn_kernel<<<256, 128>>>(x, h0, W_hh, 128, 128);   // t = 128..255 (ncu slot)
    pool_kernel<<<dim3(4, 512), 256>>>();
    out_gemm<<<dim3(8, 8), 256>>>(W_out, b_out, out);
}

// round 11
// speedup vs baseline: 1.3783x; 1.0837x over previous
#include <cuda_runtime.h>

// Problem dims
#define BATCH 512
#define LSEQ  256     // H*W = 16*16
#define CIN   32
#define HID   128
#define OUTD  512

// ---------------- scratch (static device globals; no runtime allocation) ---
__device__ float d_Wc[HID * CIN];                       // folded W_ih @ W_in  (128x32)
__device__ float d_bc[HID];                             // folded bias (incl. b_hh)
__device__ float d_hs [(size_t)BATCH * LSEQ * HID];     // 64 MB, layout [b][t][j]
__device__ float d_pooled[BATCH * HID];

// ---------------- f32x2 helpers (Blackwell packed fp32 FMA) ----------------
__device__ __forceinline__ unsigned long long pack2(float a, float b) {
    unsigned long long r;
    asm("mov.b64 %0, {%1, %2};" : "=l"(r) : "f"(a), "f"(b));
    return r;
}
__device__ __forceinline__ void unpack2(unsigned long long v, float& a, float& b) {
    asm("mov.b64 {%0, %1}, %2;" : "=f"(a), "=f"(b) : "l"(v));
}
__device__ __forceinline__ void ffma2(unsigned long long& acc,
                                      unsigned long long a, unsigned long long b) {
    asm("fma.rn.f32x2 %0, %1, %2, %0;" : "+l"(acc) : "l"(a), "l"(b));
}

// ---------------------------------------------------------------------------
// Kernel A: fold the two input linears + b_hh.
// ---------------------------------------------------------------------------
__global__ void combine_kernel(const float* __restrict__ W_in,
                               const float* __restrict__ b_in,
                               const float* __restrict__ W_ih,
                               const float* __restrict__ b_ih,
                               const float* __restrict__ b_hh) {
    int idx = blockIdx.x * blockDim.x + threadIdx.x;
    if (idx < HID * CIN) {
        int j = idx >> 5, c = idx & 31;
        float s = 0.f;
        #pragma unroll 8
        for (int m = 0; m < 64; m++) s += W_ih[j * 64 + m] * W_in[m * 32 + c];
        d_Wc[idx] = s;
    }
    if (idx < HID) {
        float s = b_ih[idx] + b_hh[idx];
        #pragma unroll 8
        for (int m = 0; m < 64; m++) s += W_ih[idx * 64 + m] * b_in[m];
        d_bc[idx] = s;
    }
}

// ---------------------------------------------------------------------------
// Marker: 1-thread no-op-ish kernel. ncu captures the 4th launch; this pads
// the sequence so rnn segment 2 lands in the profiled slot. d_pooled[0] is
// overwritten by pool_kernel, so this is semantically inert.
// ---------------------------------------------------------------------------
__global__ void marker_kernel() {
    if (threadIdx.x == 0 && blockIdx.x == 0) d_pooled[0] = d_bc[0];
}

// ---------------------------------------------------------------------------
// Kernel C: fused input-projection + sequential RNN scan, deep k-split.
//   h_t = tanh( Wc @ x[:, :, t] + bc  +  W_hh @ h_{t-1} )
// 256 CTAs x 2 batch rows, 128 threads, 2 CTAs/SM. tid = jg*8 + kc:
//   kc in [0,8): k-chunk [kc*16,+16) AND x-channel chunk [kc*4,+4)
//   jg in [0,16): thread covers j = jj*16+jg for jj in [0,8)
// Per thread per step: 10 LDS.128 (vs 32 in R10), 160 ffma2 (unchanged),
// 14-shuffle 3-level reduce-scatter over the 8 kc lanes (proj partial rides
// along). h buffers padded to 20-word chunks -> every LDS/STS covers all 32
// banks exactly. Double-buffered h and x, single RAW barrier per step.
// ---------------------------------------------------------------------------
__global__ void __launch_bounds__(128, 2) rnn_kernel(const float* __restrict__ x,
                                                     const float* __restrict__ h0,
                                                     const float* __restrict__ W_hh,
                                                     int t_first, int t_count) {
    __shared__ __align__(16) float hsm[2][2 * 160];      // [buf][row*160 + chunk*20 + off]
    __shared__ __align__(16) float xsm[2][2][16][32];    // [buf][row][tt][c]

    int tid = threadIdx.x;
    int kc = tid & 7;           // 0..7
    int jg = tid >> 3;          // 0..15
    int r0 = blockIdx.x * 2;

    // W_hh slices: 8 j rows x 16 k as pairs (64 ull = 128 regs)
    unsigned long long wp[8][8];
    #pragma unroll
    for (int jj = 0; jj < 8; jj++) {
        const float* wrow = W_hh + (jj * 16 + jg) * 128 + kc * 16;
        #pragma unroll
        for (int i = 0; i < 4; i++) {
            float4 w = *(const float4*)(wrow + i * 4);
            wp[jj][2 * i]     = pack2(w.x, w.y);
            wp[jj][2 * i + 1] = pack2(w.z, w.w);
        }
    }
    // Wc slices: 8 j rows x 4 c as pairs (16 ull = 32 regs)
    unsigned long long wc[8][2];
    #pragma unroll
    for (int jj = 0; jj < 8; jj++) {
        float4 w = *(const float4*)&d_Wc[(jj * 16 + jg) * 32 + kc * 4];
        wc[jj][0] = pack2(w.x, w.y);
        wc[jj][1] = pack2(w.z, w.w);
    }
    int j_out = kc * 16 + jg;
    float bcj = d_bc[j_out];

    // init h state: from h0 for the first segment, else from d_hs[t_first-1]
    for (int i = tid; i < 256; i += 128) {
        int r = i >> 7, k = i & 127;
        float v;
        if (t_first == 0) v = h0[(r0 + r) * 128 + k];
        else              v = d_hs[(size_t)(r0 + r) * 32768 + (t_first - 1) * 128 + k];
        hsm[0][r * 160 + (k >> 4) * 20 + (k & 15)] = v;
    }

    // x tile loader: thread (xr, xhalf, xc) loads x[b_r][c][t0+half*8 ..+8)
    int xr = tid >> 6, xhalf = (tid >> 5) & 1, xc = tid & 31;
    const float* xbase = x + ((size_t)(r0 + xr) * 32 + xc) * 256 + xhalf * 8;
    {
        int t0 = t_first;
        float4 v0 = *(const float4*)(xbase + t0);
        float4 v1 = *(const float4*)(xbase + t0 + 4);
        float* xd = &xsm[(t0 >> 4) & 1][xr][xhalf * 8][xc];
        xd[0 * 32] = v0.x; xd[1 * 32] = v0.y; xd[2 * 32] = v0.z; xd[3 * 32] = v0.w;
        xd[4 * 32] = v1.x; xd[5 * 32] = v1.y; xd[6 * 32] = v1.z; xd[7 * 32] = v1.w;
    }
    __syncthreads();

    float* oA = d_hs + (size_t)r0 * 32768 + j_out + (size_t)t_first * 128;
    float* oB = d_hs + (size_t)(r0 + 1) * 32768 + j_out + (size_t)t_first * 128;

    int hoff = kc * 20;                    // this thread's k-chunk base (words)
    int sst = kc * 20 + jg;                // STS slot (chunk kc, offset jg)

    bool b0 = (kc & 1), b1 = (kc & 2), b2 = (kc & 4);
    int t_end = t_first + t_count;

    for (int s = 0; s < t_count; s++) {
        int t = t_first + s;
        int tt = t & 15;
        int e = t >> 4;

        // prefetch next x epoch (buffer last touched 16 steps ago)
        if (tt == 0 && (t + 16) < t_end) {
            int t0 = t + 16;
            float4 v0 = *(const float4*)(xbase + t0);
            float4 v1 = *(const float4*)(xbase + t0 + 4);
            float* xd = &xsm[(e + 1) & 1][xr][xhalf * 8][xc];
            xd[0 * 32] = v0.x; xd[1 * 32] = v0.y; xd[2 * 32] = v0.z; xd[3 * 32] = v0.w;
            xd[4 * 32] = v1.x; xd[5 * 32] = v1.y; xd[6 * 32] = v1.z; xd[7 * 32] = v1.w;
        }

        const float* rbuf = hsm[t & 1];
        float* wbuf = hsm[(t + 1) & 1];

        // ---- per-(row,jj) partials over this thread's 16-k chunk + 4-c proj
        float pr[2][8];
        {
            const ulonglong2* hb = (const ulonglong2*)(rbuf + hoff);
            ulonglong2 hv0 = hb[0], hv1 = hb[1], hv2 = hb[2], hv3 = hb[3];
            ulonglong2 xv = *(const ulonglong2*)&xsm[e & 1][0][tt][kc * 4];
            #pragma unroll
            for (int jj = 0; jj < 8; jj++) {
                unsigned long long a = 0ull;
                ffma2(a, wp[jj][0], hv0.x);
                ffma2(a, wp[jj][1], hv0.y);
                ffma2(a, wp[jj][2], hv1.x);
                ffma2(a, wp[jj][3], hv1.y);
                ffma2(a, wp[jj][4], hv2.x);
                ffma2(a, wp[jj][5], hv2.y);
                ffma2(a, wp[jj][6], hv3.x);
                ffma2(a, wp[jj][7], hv3.y);
                ffma2(a, wc[jj][0], xv.x);
                ffma2(a, wc[jj][1], xv.y);
                float lo, hi; unpack2(a, lo, hi);
                pr[0][jj] = lo + hi;
            }
        }
        {
            const ulonglong2* hb = (const ulonglong2*)(rbuf + 160 + hoff);
            ulonglong2 hv0 = hb[0], hv1 = hb[1], hv2 = hb[2], hv3 = hb[3];
            ulonglong2 xv = *(const ulonglong2*)&xsm[e & 1][1][tt][kc * 4];
            #pragma unroll
            for (int jj = 0; jj < 8; jj++) {
                unsigned long long a = 0ull;
                ffma2(a, wp[jj][0], hv0.x);
                ffma2(a, wp[jj][1], hv0.y);
                ffma2(a, wp[jj][2], hv1.x);
                ffma2(a, wp[jj][3], hv1.y);
                ffma2(a, wp[jj][4], hv2.x);
                ffma2(a, wp[jj][5], hv2.y);
                ffma2(a, wp[jj][6], hv3.x);
                ffma2(a, wp[jj][7], hv3.y);
                ffma2(a, wc[jj][0], xv.x);
                ffma2(a, wc[jj][1], xv.y);
                float lo, hi; unpack2(a, lo, hi);
                pr[1][jj] = lo + hi;
            }
        }

        // ---- 3-level reduce-scatter over the 8 kc lanes ----
        // L1 (xor 1, bit b0): keep jj with (jj&1)==b0
        float q[2][4], u[2][2], f[2];
        #pragma unroll
        for (int r = 0; r < 2; r++) {
            #pragma unroll
            for (int m = 0; m < 4; m++)
                q[r][m] = (b0 ? pr[r][2 * m + 1] : pr[r][2 * m])
                        + __shfl_xor_sync(~0u, b0 ? pr[r][2 * m] : pr[r][2 * m + 1], 1);
        }
        // L2 (xor 2, bit b1): keep m with (m&1)==b1
        #pragma unroll
        for (int r = 0; r < 2; r++) {
            #pragma unroll
            for (int m = 0; m < 2; m++)
                u[r][m] = (b1 ? q[r][2 * m + 1] : q[r][2 * m])
                        + __shfl_xor_sync(~0u, b1 ? q[r][2 * m] : q[r][2 * m + 1], 2);
        }
        // L3 (xor 4, bit b2): keep s == b2  -> lane ends with jj == kc
        #pragma unroll
        for (int r = 0; r < 2; r++)
            f[r] = (b2 ? u[r][1] : u[r][0])
                 + __shfl_xor_sync(~0u, b2 ? u[r][0] : u[r][1], 4);

        float zA = f[0] + bcj;
        float zB = f[1] + bcj;
        float eA = __expf(2.0f * zA);
        float eB = __expf(2.0f * zB);
        float hAv = 1.0f - __fdividef(2.0f, eA + 1.0f);
        float hBv = 1.0f - __fdividef(2.0f, eB + 1.0f);

        wbuf[sst] = hAv;                   // chunk kc, offset jg == j_out slot
        wbuf[160 + sst] = hBv;
        oA[s * 128] = hAv;
        oB[s * 128] = hBv;

        __syncthreads();                   // RAW: h(t) + staged x visible
    }
}

// ---------------------------------------------------------------------------
// Kernel D: bilinear upsample (16->32, align_corners) + hardswish + mean pool.
// smem tile [jj][t], stride 261 -> conflict-free transposed stores and reads.
// ---------------------------------------------------------------------------
__global__ void __launch_bounds__(256) pool_kernel() {
    __shared__ float ht[32 * 261];
    __shared__ float partial[8][32];

    int tid = threadIdx.x;
    int b  = blockIdx.y;
    int j0 = blockIdx.x * 32;

    #pragma unroll
    for (int i = 0; i < 8; i++) {
        int idx4 = i * 256 + tid;
        int t = idx4 >> 3, q = idx4 & 7;
        float4 v = *(const float4*)&d_hs[((size_t)b * 256 + t) * 128 + j0 + q * 4];
        ht[(q * 4 + 0) * 261 + t] = v.x;
        ht[(q * 4 + 1) * 261 + t] = v.y;
        ht[(q * 4 + 2) * 261 + t] = v.z;
        ht[(q * 4 + 3) * 261 + t] = v.w;
    }
    __syncthreads();

    int jj = tid & 31, p = tid >> 5;
    const float* hrow = ht + jj * 261;
    float acc = 0.f;

    #pragma unroll
    for (int q = 0; q < 4; q++) {
        int oy = p * 4 + q;
        float ysf = (float)(oy * 15) / 31.0f;
        int y0 = (int)ysf;
        float wy = ysf - (float)y0;
        int y1 = min(y0 + 1, 15);

        const float* pa = hrow + y0 * 16;
        const float* pb = hrow + y1 * 16;
        float rv[16];
        #pragma unroll
        for (int xq = 0; xq < 16; xq++) {
            float a = pa[xq], c = pb[xq];
            rv[xq] = fmaf(c - a, wy, a);
        }

        #pragma unroll
        for (int ox = 0; ox < 32; ox++) {
            const int x0 = (ox * 15) / 31;
            const int x1 = (x0 + 1 < 16) ? (x0 + 1) : 15;
            const float wx = (float)(ox * 15) / 31.0f - (float)x0;
            float v = fmaf(rv[x1] - rv[x0], wx, rv[x0]);
            acc = fmaf(v, fminf(fmaxf(v + 3.0f, 0.0f), 6.0f), acc);
        }
    }

    partial[p][jj] = acc;
    __syncthreads();
    if (p == 0) {
        float s = 0.f;
        #pragma unroll
        for (int q = 0; q < 8; q++) s += partial[q][jj];
        d_pooled[b * 128 + j0 + jj] = s * (1.0f / (6.0f * 1024.0f));
    }
}

// ---------------------------------------------------------------------------
// Kernel E: out[b][o] = b_out[o] + sum_j pooled[b][j] * W_out[o][j]
// ---------------------------------------------------------------------------
__global__ void __launch_bounds__(256) out_gemm(const float* __restrict__ W_out,
                                                const float* __restrict__ b_out,
                                                float* __restrict__ out) {
    __shared__ float ws[64][65];
    __shared__ float ps[64][65];

    int tid = threadIdx.x;
    int o0 = blockIdx.x * 64, b0 = blockIdx.y * 64;
    int to = (tid & 15) * 4;
    int tb = (tid >> 4) * 4;

    float acc[4][4] = {};

    for (int k0 = 0; k0 < 128; k0 += 64) {
        __syncthreads();
        #pragma unroll
        for (int i = 0; i < 16; i++) {
            int idx = i * 256 + tid;
            int r = idx >> 6, c = idx & 63;
            ws[r][c] = W_out[(o0 + r) * 128 + k0 + c];
            ps[r][c] = d_pooled[(b0 + r) * 128 + k0 + c];
        }
        __syncthreads();

        #pragma unroll 4
        for (int k = 0; k < 64; k++) {
            float wv[4], pvv[4];
            #pragma unroll
            for (int m = 0; m < 4; m++) { wv[m] = ws[to + m][k]; pvv[m] = ps[tb + m][k]; }
            #pragma unroll
            for (int mb = 0; mb < 4; mb++)
                #pragma unroll
                for (int mo = 0; mo < 4; mo++)
                    acc[mb][mo] = fmaf(pvv[mb], wv[mo], acc[mb][mo]);
        }
    }

    #pragma unroll
    for (int mb = 0; mb < 4; mb++)
        #pragma unroll
        for (int mo = 0; mo < 4; mo++)
            out[(b0 + tb + mb) * 512 + o0 + to + mo] = acc[mb][mo] + b_out[o0 + to + mo];
}

// ---------------------------------------------------------------------------
extern "C" void kernel_launch(void* const* d_in, const int* in_sizes, int n_in,
                              void* d_out, int out_size) {
    const float* x     = (const float*)d_in[0];
    const float* h0    = (const float*)d_in[1];
    const float* W_in  = (const float*)d_in[2];
    const float* b_in  = (const float*)d_in[3];
    const float* W_ih  = (const float*)d_in[4];
    const float* b_ih  = (const float*)d_in[5];
    const float* W_hh  = (const float*)d_in[6];
    const float* b_hh  = (const float*)d_in[7];
    const float* W_out = (const float*)d_in[8];
    const float* b_out = (const float*)d_in[9];
    float* out = (float*)d_out;

    combine_kernel<<<16, 256>>>(W_in, b_in, W_ih, b_ih, b_hh);          // 1
    rnn_kernel<<<256, 128>>>(x, h0, W_hh, 0, 128);                       // 2
    marker_kernel<<<1, 32>>>();                                          // 3
    rnn_kernel<<<256, 128>>>(x, h0, W_hh, 128, 128);                     // 4 (ncu)
    pool_kernel<<<dim3(4, 512), 256>>>();                                // 5
    out_gemm<<<dim3(8, 8), 256>>>(W_out, b_out, out);                    // 6
}